// round 2
// baseline (speedup 1.0000x reference)
#include <cuda_runtime.h>
#include <cuda_bf16.h>

// Problem constants
#define BATCH  2
#define SEQ    2048
#define DMODEL 1024
#define NHEAD  16
#define HD     64
#define M_ROWS (BATCH * SEQ)     // 4096
#define NBH    (BATCH * NHEAD)   // 32

// Scratch (static device arrays — no allocation allowed)
__device__ float g_Qh[(size_t)NBH * SEQ * HD];   // [bh][s][d]
__device__ float g_Kh[(size_t)NBH * SEQ * HD];   // [bh][s][d]
__device__ float g_Vt[(size_t)NBH * HD * SEQ];   // [bh][d][s]  (transposed V)
__device__ float g_att[(size_t)M_ROWS * DMODEL]; // attended, [B*S, D]

// ---------------------------------------------------------------------------
// Generic SGEMM-NT:  C = alpha * A(MxK) * B(NxK)^T  (+ bias), row-major,
// lda = ldb = K. 128x128 tile, BK=8, 256 threads, 8x8 per thread.
// Global loads for tile k+1 are prefetched into registers before the compute
// phase of tile k (hides L2/DRAM latency behind the FMA block).
// Epilogue modes:
//   0: plain [M,N] row-major (batched via sC)
//   1: head-split   C[((b*H+h)*S + s)*HD + dd]   (m->(b,s), n->(h,dd))
//   2: head-split-T C[((b*H+h)*HD + dd)*S + s]
//   3: attended merge (batched over bh): C[(b*S+m)*D + h*HD + n]
// ---------------------------------------------------------------------------
__global__ __launch_bounds__(256) void sgemm_nt(
    const float* __restrict__ Aall, long sA,
    const float* __restrict__ Ball, long sB,
    const float* __restrict__ bias,
    float* __restrict__ Call, long sC,
    int M, int N, int K, float alpha, int mode)
{
    const float* A  = Aall + (long)blockIdx.z * sA;
    const float* Bm = Ball + (long)blockIdx.z * sB;

    __shared__ float As[8][128];
    __shared__ float Bs[8][128];

    const int tid = threadIdx.x;
    const int tx  = tid & 15;
    const int ty  = tid >> 4;

    const int row0 = blockIdx.y * 128;
    const int col0 = blockIdx.x * 128;

    // each thread loads one float4 of A and one of B per k-tile
    const int lr = tid >> 1;          // 0..127
    const int lc = (tid & 1) * 4;     // 0 or 4

    const int  gr   = row0 + lr;
    const int  gn   = col0 + lr;
    const bool aOk  = (gr < M);
    const bool bOk  = (gn < N);
    const float* Arow = A  + (long)gr * K + lc;
    const float* Brow = Bm + (long)gn * K + lc;

    float acc[8][8];
#pragma unroll
    for (int i = 0; i < 8; i++)
#pragma unroll
        for (int j = 0; j < 8; j++) acc[i][j] = 0.f;

    // prefetch k-tile 0
    float4 av = make_float4(0.f, 0.f, 0.f, 0.f);
    float4 bv = make_float4(0.f, 0.f, 0.f, 0.f);
    if (aOk) av = *reinterpret_cast<const float4*>(Arow);
    if (bOk) bv = *reinterpret_cast<const float4*>(Brow);

    for (int k0 = 0; k0 < K; k0 += 8) {
        As[lc + 0][lr] = av.x; As[lc + 1][lr] = av.y;
        As[lc + 2][lr] = av.z; As[lc + 3][lr] = av.w;
        Bs[lc + 0][lr] = bv.x; Bs[lc + 1][lr] = bv.y;
        Bs[lc + 2][lr] = bv.z; Bs[lc + 3][lr] = bv.w;
        __syncthreads();

        // prefetch next k-tile while computing this one
        if (k0 + 8 < K) {
            if (aOk) av = *reinterpret_cast<const float4*>(Arow + k0 + 8);
            if (bOk) bv = *reinterpret_cast<const float4*>(Brow + k0 + 8);
        }

#pragma unroll
        for (int kk = 0; kk < 8; kk++) {
            float4 a0 = *reinterpret_cast<const float4*>(&As[kk][ty * 4]);
            float4 a1 = *reinterpret_cast<const float4*>(&As[kk][64 + ty * 4]);
            float4 b0 = *reinterpret_cast<const float4*>(&Bs[kk][tx * 4]);
            float4 b1 = *reinterpret_cast<const float4*>(&Bs[kk][64 + tx * 4]);
            float ar[8] = {a0.x, a0.y, a0.z, a0.w, a1.x, a1.y, a1.z, a1.w};
            float br[8] = {b0.x, b0.y, b0.z, b0.w, b1.x, b1.y, b1.z, b1.w};
#pragma unroll
            for (int i = 0; i < 8; i++)
#pragma unroll
                for (int j = 0; j < 8; j++)
                    acc[i][j] = fmaf(ar[i], br[j], acc[i][j]);
        }
        __syncthreads();
    }

    int rm[8], cn[8];
#pragma unroll
    for (int i = 0; i < 4; i++) {
        rm[i]     = row0 + ty * 4 + i;
        rm[i + 4] = row0 + 64 + ty * 4 + i;
    }
#pragma unroll
    for (int j = 0; j < 4; j++) {
        cn[j]     = col0 + tx * 4 + j;
        cn[j + 4] = col0 + 64 + tx * 4 + j;
    }

#pragma unroll
    for (int i = 0; i < 8; i++) {
        const int m = rm[i];
        if (m >= M) continue;
#pragma unroll
        for (int j = 0; j < 8; j++) {
            const int n = cn[j];
            if (n >= N) continue;
            float c = acc[i][j] * alpha;
            if (bias) c += bias[n];
            long idx;
            if (mode == 0) {
                idx = (long)blockIdx.z * sC + (long)m * N + n;
            } else if (mode == 1) {
                int b = m >> 11, s = m & 2047, h = n >> 6, dd = n & 63;
                idx = (((long)(b * NHEAD + h) * SEQ) + s) * HD + dd;
            } else if (mode == 2) {
                int b = m >> 11, s = m & 2047, h = n >> 6, dd = n & 63;
                idx = ((long)(b * NHEAD + h) * HD + dd) * SEQ + s;
            } else {
                int bh = blockIdx.z;
                int b = bh >> 4, h = bh & 15;
                idx = ((long)(b * SEQ + m)) * DMODEL + h * HD + n;
            }
            Call[idx] = c;
        }
    }
}

// ---------------------------------------------------------------------------
// In-place row softmax: one block (256 threads) per row of length SEQ=2048.
// Each thread holds 8 values in registers (2 float4), so one read + one write.
// ---------------------------------------------------------------------------
__global__ __launch_bounds__(256) void softmax_rows(float* __restrict__ P)
{
    const long row = blockIdx.x;
    float* p = P + row * (long)SEQ;
    const int tid = threadIdx.x;

    float4 v0 = reinterpret_cast<float4*>(p)[tid * 2 + 0];
    float4 v1 = reinterpret_cast<float4*>(p)[tid * 2 + 1];

    float mx = fmaxf(fmaxf(fmaxf(v0.x, v0.y), fmaxf(v0.z, v0.w)),
                     fmaxf(fmaxf(v1.x, v1.y), fmaxf(v1.z, v1.w)));
#pragma unroll
    for (int o = 16; o; o >>= 1) mx = fmaxf(mx, __shfl_xor_sync(0xffffffffu, mx, o));

    __shared__ float redm[8];
    __shared__ float reds[8];
    const int warp = tid >> 5, lane = tid & 31;
    if (lane == 0) redm[warp] = mx;
    __syncthreads();
    mx = redm[0];
#pragma unroll
    for (int i = 1; i < 8; i++) mx = fmaxf(mx, redm[i]);

    v0.x = __expf(v0.x - mx); v0.y = __expf(v0.y - mx);
    v0.z = __expf(v0.z - mx); v0.w = __expf(v0.w - mx);
    v1.x = __expf(v1.x - mx); v1.y = __expf(v1.y - mx);
    v1.z = __expf(v1.z - mx); v1.w = __expf(v1.w - mx);

    float sum = v0.x + v0.y + v0.z + v0.w + v1.x + v1.y + v1.z + v1.w;
#pragma unroll
    for (int o = 16; o; o >>= 1) sum += __shfl_xor_sync(0xffffffffu, sum, o);
    if (lane == 0) reds[warp] = sum;
    __syncthreads();
    sum = reds[0];
#pragma unroll
    for (int i = 1; i < 8; i++) sum += reds[i];

    const float inv = 1.0f / sum;
    v0.x *= inv; v0.y *= inv; v0.z *= inv; v0.w *= inv;
    v1.x *= inv; v1.y *= inv; v1.z *= inv; v1.w *= inv;

    reinterpret_cast<float4*>(p)[tid * 2 + 0] = v0;
    reinterpret_cast<float4*>(p)[tid * 2 + 1] = v1;
}

// ---------------------------------------------------------------------------
extern "C" void kernel_launch(void* const* d_in, const int* in_sizes, int n_in,
                              void* d_out, int out_size)
{
    const float* query = (const float*)d_in[0];
    const float* key_  = (const float*)d_in[1];
    const float* value = (const float*)d_in[2];
    const float* Wq = (const float*)d_in[3];
    const float* bq = (const float*)d_in[4];
    const float* Wk = (const float*)d_in[5];
    const float* bk = (const float*)d_in[6];
    const float* Wv = (const float*)d_in[7];
    const float* bv = (const float*)d_in[8];
    const float* Wo = (const float*)d_in[9];
    const float* bo = (const float*)d_in[10];

    float* out   = (float*)d_out;                          // [B,S,D]
    float* attnW = out + (long)M_ROWS * DMODEL;            // [B,H,S,S]

    void *pQ, *pK, *pV, *pAtt;
    cudaGetSymbolAddress(&pQ, g_Qh);
    cudaGetSymbolAddress(&pK, g_Kh);
    cudaGetSymbolAddress(&pV, g_Vt);
    cudaGetSymbolAddress(&pAtt, g_att);
    float* Qh  = (float*)pQ;
    float* Kh  = (float*)pK;
    float* Vt  = (float*)pV;
    float* att = (float*)pAtt;

    const dim3 gridProj(DMODEL / 128, M_ROWS / 128, 1);    // (8, 32)
    const dim3 gridQK(SEQ / 128, SEQ / 128, NBH);          // (16, 16, 32)
    const dim3 gridPV(1, SEQ / 128, NBH);                  // (1, 16, 32)
    const dim3 blk(256);

    // Q/K/V projections -> head-split scratch
    sgemm_nt<<<gridProj, blk>>>(query, 0, Wq, 0, bq, Qh, 0,
                                M_ROWS, DMODEL, DMODEL, 1.0f, 1);
    sgemm_nt<<<gridProj, blk>>>(key_,  0, Wk, 0, bk, Kh, 0,
                                M_ROWS, DMODEL, DMODEL, 1.0f, 1);
    sgemm_nt<<<gridProj, blk>>>(value, 0, Wv, 0, bv, Vt, 0,
                                M_ROWS, DMODEL, DMODEL, 1.0f, 2);

    // Scores = (1/8) * Q K^T, written straight into the attention_weights slot
    sgemm_nt<<<gridQK, blk>>>(Qh, (long)SEQ * HD, Kh, (long)SEQ * HD, nullptr,
                              attnW, (long)SEQ * SEQ,
                              SEQ, SEQ, HD, 0.125f, 0);

    // Row softmax in place (this IS output #2)
    softmax_rows<<<NBH * SEQ, blk>>>(attnW);

    // attended = P @ V  (V pre-transposed so this is also NT), merge heads
    sgemm_nt<<<gridPV, blk>>>(attnW, (long)SEQ * SEQ, Vt, (long)HD * SEQ, nullptr,
                              att, 0,
                              SEQ, HD, SEQ, 1.0f, 3);

    // output = attended @ Wo^T + bo -> output #1
    sgemm_nt<<<gridProj, blk>>>(att, 0, Wo, 0, bo, out, 0,
                                M_ROWS, DMODEL, DMODEL, 1.0f, 0);
}

// round 5
// speedup vs baseline: 2.5554x; 2.5554x over previous
#include <cuda_runtime.h>
#include <cstdint>

// Problem constants
#define BATCH  2
#define SEQ    2048
#define DMODEL 1024
#define NHEAD  16
#define HD     64
#define M_ROWS (BATCH * SEQ)     // 4096
#define NBH    (BATCH * NHEAD)   // 32

// Scratch (static device arrays — no allocation allowed)
__device__ float g_Qh[(size_t)NBH * SEQ * HD];   // [bh][s][d]
__device__ float g_Kh[(size_t)NBH * SEQ * HD];   // [bh][s][d]
__device__ float g_Vt[(size_t)NBH * HD * SEQ];   // [bh][d][s]  (transposed V)
__device__ float g_att[(size_t)M_ROWS * DMODEL]; // attended, [B*S, D]

// round fp32 -> tf32 (rna): unbiased, halves tensor-core truncation error
__device__ __forceinline__ float rtf(float x) {
    uint32_t u;
    asm("cvt.rna.tf32.f32 %0, %1;" : "=r"(u) : "f"(x));
    return __uint_as_float(u);
}

// m16n8k8 tf32 MMA (row.col), f32 accumulate
__device__ __forceinline__ void mma_tf32(float* d, const uint32_t* a,
                                         uint32_t b0, uint32_t b1) {
    asm volatile(
        "mma.sync.aligned.m16n8k8.row.col.f32.tf32.tf32.f32 "
        "{%0,%1,%2,%3}, {%4,%5,%6,%7}, {%8,%9}, {%0,%1,%2,%3};"
        : "+f"(d[0]), "+f"(d[1]), "+f"(d[2]), "+f"(d[3])
        : "r"(a[0]), "r"(a[1]), "r"(a[2]), "r"(a[3]), "r"(b0), "r"(b1));
}

// output index by layout mode
__device__ __forceinline__ long out_idx(int mode, int z, long sC, int Nfull,
                                        int m, int n) {
    if (mode == 0) return (long)z * sC + (long)m * Nfull + n;
    if (mode == 1) {
        int b = m >> 11, s = m & 2047, h = n >> 6, dd = n & 63;
        return (((long)(b * NHEAD + h) * SEQ) + s) * HD + dd;
    }
    if (mode == 2) {
        int b = m >> 11, s = m & 2047, h = n >> 6, dd = n & 63;
        return ((long)(b * NHEAD + h) * HD + dd) * SEQ + s;
    }
    int b = z >> 4, h = z & 15;
    return ((long)(b * SEQ + m)) * DMODEL + h * HD + n;
}

// ===========================================================================
// tf32 mma.sync GEMM-NT:  C = alpha * A(MxK) * B(NxK)^T (+ bias)
// CTA tile 128 x NTILE (NTILE = 1<<NSH), BK=32, 256 threads = 8 warps (4m x 2n),
// warp tile 32 x NTILE/2.  Smem stride 36 floats -> fragment LDS bank = lane
// (conflict-free).  Next chunk's globals prefetched into registers.
// All launch shapes are exact tile multiples — no bounds checks.
// ===========================================================================
template <int NSH>
__global__ __launch_bounds__(256) void gemm_mma(
    const float* __restrict__ Aall, long sA,
    const float* __restrict__ Ball, long sB,
    const float* __restrict__ bias,
    float* __restrict__ Call, long sC,
    int Nfull, int K, float alpha, int mode)
{
    constexpr int NTILE = 1 << NSH;
    constexpr int WN  = NTILE / 2;      // warp col extent (64 or 32)
    constexpr int NJ  = WN / 8;         // n8 tiles per warp (8 or 4)
    constexpr int NBI = NTILE / 32;     // B float4 staging iters (4 or 2)
    constexpr int SKA = 36;             // smem row stride in floats

    __shared__ float As[128 * SKA];
    __shared__ float Bs[NTILE * SKA];

    const int tid  = threadIdx.x;
    const int wid  = tid >> 5;
    const int lane = tid & 31;
    const int wm = wid >> 1, wn = wid & 1;
    const int gq = lane >> 2, qt = lane & 3;     // quad row / thread-in-quad
    const int z  = blockIdx.z;

    const float* A = Aall + (long)z * sA;
    const float* B = Ball + (long)z * sB;
    const int m0 = blockIdx.y << 7;
    const int n0 = blockIdx.x << NSH;

    const float* Abase = A + (long)m0 * K;
    const float* Bbase = B + (long)n0 * K;

    float acc[2][NJ][4];
#pragma unroll
    for (int i = 0; i < 2; ++i)
#pragma unroll
        for (int j = 0; j < NJ; ++j)
#pragma unroll
            for (int e = 0; e < 4; ++e) acc[i][j][e] = 0.f;

    // prefetch chunk 0 into registers
    float4 pA[4], pB[NBI];
#pragma unroll
    for (int it = 0; it < 4; ++it) {
        int idx = tid + (it << 8), r = idx >> 3, c4 = idx & 7;
        pA[it] = *reinterpret_cast<const float4*>(Abase + (long)r * K + (c4 << 2));
    }
#pragma unroll
    for (int it = 0; it < NBI; ++it) {
        int idx = tid + (it << 8), r = idx >> 3, c4 = idx & 7;
        pB[it] = *reinterpret_cast<const float4*>(Bbase + (long)r * K + (c4 << 2));
    }

    const int NC = K >> 5;
    for (int ch = 0; ch < NC; ++ch) {
        // commit prefetched chunk to smem (tf32-rounded)
#pragma unroll
        for (int it = 0; it < 4; ++it) {
            int idx = tid + (it << 8), r = idx >> 3, c4 = idx & 7;
            float4 v = pA[it];
            v.x = rtf(v.x); v.y = rtf(v.y); v.z = rtf(v.z); v.w = rtf(v.w);
            *reinterpret_cast<float4*>(As + r * SKA + (c4 << 2)) = v;
        }
#pragma unroll
        for (int it = 0; it < NBI; ++it) {
            int idx = tid + (it << 8), r = idx >> 3, c4 = idx & 7;
            float4 v = pB[it];
            v.x = rtf(v.x); v.y = rtf(v.y); v.z = rtf(v.z); v.w = rtf(v.w);
            *reinterpret_cast<float4*>(Bs + r * SKA + (c4 << 2)) = v;
        }
        __syncthreads();

        // prefetch next chunk while computing this one
        if (ch + 1 < NC) {
            const float* An = Abase + (ch + 1) * 32;
            const float* Bn = Bbase + (ch + 1) * 32;
#pragma unroll
            for (int it = 0; it < 4; ++it) {
                int idx = tid + (it << 8), r = idx >> 3, c4 = idx & 7;
                pA[it] = *reinterpret_cast<const float4*>(An + (long)r * K + (c4 << 2));
            }
#pragma unroll
            for (int it = 0; it < NBI; ++it) {
                int idx = tid + (it << 8), r = idx >> 3, c4 = idx & 7;
                pB[it] = *reinterpret_cast<const float4*>(Bn + (long)r * K + (c4 << 2));
            }
        }

        const float* Aw = As + (wm * 32) * SKA;
        const float* Bw = Bs + (wn * WN) * SKA;
#pragma unroll
        for (int ks = 0; ks < 4; ++ks) {
            const int k = ks << 3;
            uint32_t af[2][4];
#pragma unroll
            for (int i = 0; i < 2; ++i) {
                const float* ap = Aw + (i * 16 + gq) * SKA + k + qt;
                af[i][0] = __float_as_uint(ap[0]);
                af[i][1] = __float_as_uint(ap[8 * SKA]);
                af[i][2] = __float_as_uint(ap[4]);
                af[i][3] = __float_as_uint(ap[8 * SKA + 4]);
            }
#pragma unroll
            for (int j = 0; j < NJ; ++j) {
                const float* bp = Bw + (j * 8 + gq) * SKA + k + qt;
                uint32_t b0 = __float_as_uint(bp[0]);
                uint32_t b1 = __float_as_uint(bp[4]);
#pragma unroll
                for (int i = 0; i < 2; ++i)
                    mma_tf32(acc[i][j], af[i], b0, b1);
            }
        }
        __syncthreads();
    }

    // epilogue: direct global stores (float2 when n-contiguous)
#pragma unroll
    for (int i = 0; i < 2; ++i) {
#pragma unroll
        for (int j = 0; j < NJ; ++j) {
            const int r0 = m0 + wm * 32 + i * 16 + gq;
            const int c0 = n0 + wn * WN + j * 8 + (qt << 1);
            float v0 = acc[i][j][0] * alpha, v1 = acc[i][j][1] * alpha;
            float v2 = acc[i][j][2] * alpha, v3 = acc[i][j][3] * alpha;
            if (bias) {
                float b0 = bias[c0], b1 = bias[c0 + 1];
                v0 += b0; v1 += b1; v2 += b0; v3 += b1;
            }
            if (mode != 2) {
                *reinterpret_cast<float2*>(&Call[out_idx(mode, z, sC, Nfull, r0,     c0)]) = make_float2(v0, v1);
                *reinterpret_cast<float2*>(&Call[out_idx(mode, z, sC, Nfull, r0 + 8, c0)]) = make_float2(v2, v3);
            } else {
                Call[out_idx(2, z, sC, Nfull, r0,     c0)]     = v0;
                Call[out_idx(2, z, sC, Nfull, r0,     c0 + 1)] = v1;
                Call[out_idx(2, z, sC, Nfull, r0 + 8, c0)]     = v2;
                Call[out_idx(2, z, sC, Nfull, r0 + 8, c0 + 1)] = v3;
            }
        }
    }
}

// ---------------------------------------------------------------------------
// In-place row softmax: one block (256 threads) per row of length SEQ=2048.
// ---------------------------------------------------------------------------
__global__ __launch_bounds__(256) void softmax_rows(float* __restrict__ P)
{
    const long row = blockIdx.x;
    float* p = P + row * (long)SEQ;
    const int tid = threadIdx.x;

    float4 v0 = reinterpret_cast<float4*>(p)[tid * 2 + 0];
    float4 v1 = reinterpret_cast<float4*>(p)[tid * 2 + 1];

    float mx = fmaxf(fmaxf(fmaxf(v0.x, v0.y), fmaxf(v0.z, v0.w)),
                     fmaxf(fmaxf(v1.x, v1.y), fmaxf(v1.z, v1.w)));
#pragma unroll
    for (int o = 16; o; o >>= 1) mx = fmaxf(mx, __shfl_xor_sync(0xffffffffu, mx, o));

    __shared__ float redm[8];
    __shared__ float reds[8];
    const int warp = tid >> 5, lane = tid & 31;
    if (lane == 0) redm[warp] = mx;
    __syncthreads();
    mx = redm[0];
#pragma unroll
    for (int i = 1; i < 8; i++) mx = fmaxf(mx, redm[i]);

    v0.x = __expf(v0.x - mx); v0.y = __expf(v0.y - mx);
    v0.z = __expf(v0.z - mx); v0.w = __expf(v0.w - mx);
    v1.x = __expf(v1.x - mx); v1.y = __expf(v1.y - mx);
    v1.z = __expf(v1.z - mx); v1.w = __expf(v1.w - mx);

    float sum = v0.x + v0.y + v0.z + v0.w + v1.x + v1.y + v1.z + v1.w;
#pragma unroll
    for (int o = 16; o; o >>= 1) sum += __shfl_xor_sync(0xffffffffu, sum, o);
    if (lane == 0) reds[warp] = sum;
    __syncthreads();
    sum = reds[0];
#pragma unroll
    for (int i = 1; i < 8; i++) sum += reds[i];

    const float inv = 1.0f / sum;
    v0.x *= inv; v0.y *= inv; v0.z *= inv; v0.w *= inv;
    v1.x *= inv; v1.y *= inv; v1.z *= inv; v1.w *= inv;

    reinterpret_cast<float4*>(p)[tid * 2 + 0] = v0;
    reinterpret_cast<float4*>(p)[tid * 2 + 1] = v1;
}

// ---------------------------------------------------------------------------
extern "C" void kernel_launch(void* const* d_in, const int* in_sizes, int n_in,
                              void* d_out, int out_size)
{
    const float* query = (const float*)d_in[0];
    const float* key_  = (const float*)d_in[1];
    const float* value = (const float*)d_in[2];
    const float* Wq = (const float*)d_in[3];
    const float* bq = (const float*)d_in[4];
    const float* Wk = (const float*)d_in[5];
    const float* bk = (const float*)d_in[6];
    const float* Wv = (const float*)d_in[7];
    const float* bv = (const float*)d_in[8];
    const float* Wo = (const float*)d_in[9];
    const float* bo = (const float*)d_in[10];

    float* out   = (float*)d_out;                          // [B,S,D]
    float* attnW = out + (long)M_ROWS * DMODEL;            // [B,H,S,S]

    void *pQ, *pK, *pV, *pAtt;
    cudaGetSymbolAddress(&pQ, g_Qh);
    cudaGetSymbolAddress(&pK, g_Kh);
    cudaGetSymbolAddress(&pV, g_Vt);
    cudaGetSymbolAddress(&pAtt, g_att);
    float* Qh  = (float*)pQ;
    float* Kh  = (float*)pK;
    float* Vt  = (float*)pV;
    float* att = (float*)pAtt;

    const dim3 blk(256);
    const dim3 gridProj(DMODEL / 128, M_ROWS / 128, 1);    // (8, 32)
    const dim3 gridQK(SEQ / 128, SEQ / 128, NBH);          // (16, 16, 32)
    const dim3 gridPV(1, SEQ / 128, NBH);                  // (1, 16, 32)

    // Q/K/V projections -> head-split scratch (tf32 tensor cores)
    gemm_mma<7><<<gridProj, blk>>>(query, 0, Wq, 0, bq, Qh, 0,
                                   DMODEL, DMODEL, 1.0f, 1);
    gemm_mma<7><<<gridProj, blk>>>(key_,  0, Wk, 0, bk, Kh, 0,
                                   DMODEL, DMODEL, 1.0f, 1);
    gemm_mma<7><<<gridProj, blk>>>(value, 0, Wv, 0, bv, Vt, 0,
                                   DMODEL, DMODEL, 1.0f, 2);

    // Scores = (1/8) * Q K^T straight into the attention_weights slot
    gemm_mma<7><<<gridQK, blk>>>(Qh, (long)SEQ * HD, Kh, (long)SEQ * HD,
                                 nullptr, attnW, (long)SEQ * SEQ,
                                 SEQ, HD, 0.125f, 0);

    // Row softmax in place (this IS output #2)
    softmax_rows<<<NBH * SEQ, blk>>>(attnW);

    // attended = P @ V (V pre-transposed -> NT), merge heads.  NTILE=64
    gemm_mma<6><<<gridPV, blk>>>(attnW, (long)SEQ * SEQ, Vt, (long)HD * SEQ,
                                 nullptr, att, 0,
                                 HD, SEQ, 1.0f, 3);

    // output = attended @ Wo^T + bo -> output #1
    gemm_mma<7><<<gridProj, blk>>>(att, 0, Wo, 0, bo, out, 0,
                                   DMODEL, DMODEL, 1.0f, 0);
}